// round 15
// baseline (speedup 1.0000x reference)
#include <cuda_runtime.h>
#include <cuda_bf16.h>
#include <stdint.h>

#define DEV __device__ __forceinline__
typedef unsigned long long ull;

#define B_ 1024
#define U_ 512
#define SIGD 16512

// ---------- scratch ----------
__device__ float d_skip[B_ * 3];
__device__ float d_sigw[B_ * 3];
__device__ __align__(16) float d_z[B_ * 1536];
__device__ __align__(16) float d_aggin[3 * B_ * 128];
__device__ __align__(16) float d_subE[3 * B_ * 1152];
__device__ __align__(16) float d_subW[3 * 1152 * 128];
__device__ __align__(16) float d_agg[B_ * 384];
__device__ __align__(16) float d_part[8 * B_ * U_];

// ---------- helpers ----------
DEV float sigm(float x) { return 1.f / (1.f + __expf(-x)); }
DEV uint32_t f2tf(float f) {
    uint32_t r;
    asm("cvt.rna.tf32.f32 %0,%1;" : "=r"(r) : "f"(f));
    return r;
}
DEV void mma_tf32(float acc[4], const uint32_t a[4], const uint32_t b[2]) {
    asm volatile(
        "mma.sync.aligned.m16n8k8.row.col.f32.tf32.tf32.f32 "
        "{%0,%1,%2,%3},{%4,%5,%6,%7},{%8,%9},{%0,%1,%2,%3};"
        : "+f"(acc[0]), "+f"(acc[1]), "+f"(acc[2]), "+f"(acc[3])
        : "r"(a[0]), "r"(a[1]), "r"(a[2]), "r"(a[3]), "r"(b[0]), "r"(b[1]));
}

DEV void kan_expand(float xn, float e[9]) {
    e[0] = xn * sigm(xn);
#pragma unroll
    for (int j = 1; j < 9; j++) e[j] = 0.f;
    float tp = (xn + 2.2f) * 2.5f;
    float tf = floorf(tp);
    if (tf >= 0.f && tf <= 10.f) {
        int t = (int)tf;
        float u = tp - tf, u2 = u * u, u3 = u2 * u, omu = 1.f - u;
        float v0 = omu * omu * omu * (1.f / 6.f);
        float v1 = (3.f * u3 - 6.f * u2 + 4.f) * (1.f / 6.f);
        float v2 = (-3.f * u3 + 3.f * u2 + 3.f * u + 1.f) * (1.f / 6.f);
        float v3 = u3 * (1.f / 6.f);
        if (t >= 3)           e[t - 2] = v0;
        if (t >= 2 && t <= 9) e[t - 1] = v1;
        if (t >= 1 && t <= 8) e[t]     = v2;
        if (t <= 7)           e[t + 1] = v3;
    }
}

DEV float red128s(float v, float* sh) {
    int t = threadIdx.x;
    sh[t] = v; __syncthreads();
#pragma unroll
    for (int s = 64; s > 0; s >>= 1) { if (t < s) sh[t] += sh[t + s]; __syncthreads(); }
    float r = sh[0]; __syncthreads();
    return r;
}
DEV float red256s(float v, float* sh) {
    int t = threadIdx.x;
    sh[t] = v; __syncthreads();
#pragma unroll
    for (int s = 128; s > 0; s >>= 1) { if (t < s) sh[t] += sh[t + s]; __syncthreads(); }
    float r = sh[0]; __syncthreads();
    return r;
}

// =========================================================================
// K-MEGA: MMA (0..255) + skip (256..1279) + z (1280..1375)
//         + aggin (1376..1471) + packW (1472..3199)
// =========================================================================
#define LDA4 76
#define LDB4 136
#define SM_MEGA (23904 * 4)   // 95616 bytes

DEV void mma_body(int bid, const float* __restrict__ x,
                  const float* __restrict__ lng, const float* __restrict__ lnb,
                  const float* __restrict__ wb, const float* __restrict__ ws,
                  uint32_t* sm4) {
    uint32_t* As4 = sm4;
    uint32_t* Bs4 = sm4 + 9728;
    float* lngS = (float*)(sm4 + 19520);
    float* lnbS = (float*)(sm4 + 21584);
    float* mus  = (float*)(sm4 + 23648);
    float* rss  = (float*)(sm4 + 23776);

    int tid = threadIdx.x, lane = tid & 31, wid = tid >> 5;
    int ks = bid & 7, mg = (bid >> 3) & 7, ng = bid >> 6;
    int rowBase = mg * 128, colBase = ng * 128;
    int warpRow = (wid & 3) * 32, warpCol = (wid >> 2) * 64;
    int g = lane >> 2, tg = lane & 3;
    int rsel = wid, n4 = lane * 4;
    int ksBase = ks * 2064;

#pragma unroll 1
    for (int rr = 0; rr < 16; rr++) {
        int row = wid * 16 + rr;
        float4 v = *(const float4*)(x + (size_t)(rowBase + row) * 128 + lane * 4);
        float s = v.x + v.y + v.z + v.w;
        float q = v.x * v.x + v.y * v.y + v.z * v.z + v.w * v.w;
#pragma unroll
        for (int off = 16; off > 0; off >>= 1) {
            s += __shfl_xor_sync(0xFFFFFFFFu, s, off);
            q += __shfl_xor_sync(0xFFFFFFFFu, q, off);
        }
        if (lane == 0) {
            float mean = (s + 0.5f * s * s) / (float)SIGD;
            float m2 = (q + 0.25f * q * q) / (float)SIGD;
            mus[row] = mean;
            rss[row] = rsqrtf(m2 - mean * mean + 1e-3f);
        }
    }
    for (int i = tid; i < 2064; i += 256) {
        lngS[i] = lng[ksBase + i];
        lnbS[i] = lnb[ksBase + i];
    }
    __syncthreads();

    float acc[2][8][4];
#pragma unroll
    for (int mi = 0; mi < 2; mi++)
#pragma unroll
        for (int ni = 0; ni < 8; ni++)
#pragma unroll
            for (int q = 0; q < 4; q++) acc[mi][ni][q] = 0.f;

    for (int ch = 0; ch < 258; ch++) {
        int f0 = ksBase + ch * 8;
        int l0 = ch * 8;
        // --- A expand: store with in-8-group k permutation for paired loads ---
#pragma unroll
        for (int p = 0; p < 4; p++) {
            int task = tid + p * 256;
            int fl = task & 7, row = task >> 3;
            int fg = f0 + fl;
            const float* xr = x + (size_t)(rowBase + row) * 128;
            float val;
            if (fg < 128) val = __ldg(xr + fg);
            else {
                int q = fg - 128;
                val = 0.5f * __ldg(xr + (q >> 7)) * __ldg(xr + (q & 127));
            }
            float xn = (val - mus[row]) * rss[row] * lngS[l0 + fl] + lnbS[l0 + fl];
            float e[9];
            kan_expand(xn, e);
            int rbase = row * LDA4;
            int kb = fl * 9;
#pragma unroll
            for (int j = 0; j < 9; j++) {
                int k = kb + j;
                int pk = (k & ~7) | ((k & 3) << 1) | ((k >> 2) & 1);
                As4[rbase + pk] = f2tf(e[j]);
            }
        }
#pragma unroll
        for (int i = 0; i < 9; i++) {
            int kl = i * 8 + rsel;
            int kg = f0 * 9 + kl;
            int f = kg / 9, jj = kg - f * 9;
            const float* p = (jj == 0) ? wb + (size_t)f * 512
                                       : ws + ((size_t)f * 8 + (jj - 1)) * 512;
            float4 v = *(const float4*)(p + colBase + n4);
            uint4 w;
            w.x = f2tf(v.x); w.y = f2tf(v.y); w.z = f2tf(v.z); w.w = f2tf(v.w);
            *(uint4*)&Bs4[kl * LDB4 + n4] = w;
        }
        __syncthreads();
#pragma unroll 3
        for (int ks2 = 0; ks2 < 9; ks2++) {
            int k0 = ks2 * 8;
            uint32_t aF[2][4];
#pragma unroll
            for (int mi = 0; mi < 2; mi++) {
                int r = warpRow + mi * 16;
                uint2 A01 = *(const uint2*)&As4[(r + g) * LDA4 + k0 + tg * 2];
                uint2 A23 = *(const uint2*)&As4[(r + 8 + g) * LDA4 + k0 + tg * 2];
                aF[mi][0] = A01.x; aF[mi][1] = A23.x;
                aF[mi][2] = A01.y; aF[mi][3] = A23.y;
            }
            uint32_t bF[8][2];
#pragma unroll
            for (int ni = 0; ni < 8; ni++) {
                int c = warpCol + ni * 8 + g;
                bF[ni][0] = Bs4[(k0 + tg) * LDB4 + c];
                bF[ni][1] = Bs4[(k0 + tg + 4) * LDB4 + c];
            }
#pragma unroll
            for (int mi = 0; mi < 2; mi++)
#pragma unroll
                for (int ni = 0; ni < 8; ni++)
                    mma_tf32(acc[mi][ni], aF[mi], bF[ni]);
        }
        __syncthreads();
    }
    float* dp = d_part + (size_t)ks * (B_ * U_);
#pragma unroll
    for (int mi = 0; mi < 2; mi++)
#pragma unroll
        for (int ni = 0; ni < 8; ni++) {
            int row = rowBase + warpRow + mi * 16 + g;
            int col = colBase + warpCol + ni * 8 + tg * 2;
            *(float2*)&dp[(size_t)row * 512 + col] = make_float2(acc[mi][ni][0], acc[mi][ni][1]);
            *(float2*)&dp[(size_t)(row + 8) * 512 + col] = make_float2(acc[mi][ni][2], acc[mi][ni][3]);
        }
}

DEV void skip_body(int b, const float* __restrict__ x,
                   const float* __restrict__ skw, const float* __restrict__ skb,
                   uint32_t* sm4) {
    float* xs = (float*)sm4;
    float* sh = xs + 128;
    int t = threadIdx.x;
    if (t < 128) xs[t] = x[b * 128 + t];
    __syncthreads();
    float a0 = 0.f, a1 = 0.f, a2 = 0.f;
    for (int i = t; i < SIGD; i += 256) {
        float sv = (i < 128) ? xs[i] : 0.5f * xs[(i - 128) >> 7] * xs[(i - 128) & 127];
        a0 += sv * skw[i * 3 + 0];
        a1 += sv * skw[i * 3 + 1];
        a2 += sv * skw[i * 3 + 2];
    }
    a0 = red256s(a0, sh); a1 = red256s(a1, sh); a2 = red256s(a2, sh);
    if (t == 0) {
        d_skip[b * 3 + 0] = a0 + skb[0];
        d_skip[b * 3 + 1] = a1 + skb[1];
        d_skip[b * 3 + 2] = a2 + skb[2];
    }
}

#define LDAZ 36
#define LDBZ 136
DEV void z_body(int zb, const float* __restrict__ x, const float* __restrict__ h0,
                const float* __restrict__ W1, const float* __restrict__ W2,
                const float* __restrict__ bias, uint32_t* sm4) {
    uint32_t* As4 = sm4;
    uint32_t* Bs4 = sm4 + 4608;
    int tid = threadIdx.x, lane = tid & 31, wid = tid >> 5;
    int colBase = (zb % 12) * 128, rowBase = (zb / 12) * 128;
    int warpRow = (wid & 3) * 32, warpCol = (wid >> 2) * 64;
    int g = lane >> 2, tg = lane & 3;
    int rsel = wid, n4 = lane * 4;
    int arow = tid >> 1, ahalf = tid & 1;

    float acc[2][8][4];
#pragma unroll
    for (int mi = 0; mi < 2; mi++)
#pragma unroll
        for (int ni = 0; ni < 8; ni++)
#pragma unroll
            for (int q = 0; q < 4; q++) acc[mi][ni][q] = 0.f;

    for (int kt = 0; kt < 640; kt += 32) {
        const float* src = (kt < 128) ? x + (size_t)(rowBase + arow) * 128 + kt + ahalf * 16
                                      : h0 + (size_t)(rowBase + arow) * 512 + (kt - 128) + ahalf * 16;
#pragma unroll
        for (int q = 0; q < 4; q++) {
            float4 v = *(const float4*)(src + q * 4);
            uint4 w;
            w.x = f2tf(v.x); w.y = f2tf(v.y); w.z = f2tf(v.z); w.w = f2tf(v.w);
            *(uint4*)&As4[arow * LDAZ + ahalf * 16 + q * 4] = w;
        }
#pragma unroll
        for (int i = 0; i < 4; i++) {
            int kl = i * 8 + rsel;
            int kg = kt + kl;
            const float* p = (kg < 128) ? W1 + (size_t)kg * 1536 + colBase + n4
                                        : W2 + (size_t)(kg - 128) * 1536 + colBase + n4;
            float4 v = *(const float4*)p;
            uint4 w;
            w.x = f2tf(v.x); w.y = f2tf(v.y); w.z = f2tf(v.z); w.w = f2tf(v.w);
            *(uint4*)&Bs4[kl * LDBZ + n4] = w;
        }
        __syncthreads();
#pragma unroll
        for (int ks2 = 0; ks2 < 4; ks2++) {
            int k0 = ks2 * 8;
            uint32_t aF[2][4];
#pragma unroll
            for (int mi = 0; mi < 2; mi++) {
                int r = warpRow + mi * 16;
                aF[mi][0] = As4[(r + g) * LDAZ + k0 + tg];
                aF[mi][1] = As4[(r + 8 + g) * LDAZ + k0 + tg];
                aF[mi][2] = As4[(r + g) * LDAZ + k0 + tg + 4];
                aF[mi][3] = As4[(r + 8 + g) * LDAZ + k0 + tg + 4];
            }
            uint32_t bF[8][2];
#pragma unroll
            for (int ni = 0; ni < 8; ni++) {
                int c = warpCol + ni * 8 + g;
                bF[ni][0] = Bs4[(k0 + tg) * LDBZ + c];
                bF[ni][1] = Bs4[(k0 + tg + 4) * LDBZ + c];
            }
#pragma unroll
            for (int mi = 0; mi < 2; mi++)
#pragma unroll
                for (int ni = 0; ni < 8; ni++)
                    mma_tf32(acc[mi][ni], aF[mi], bF[ni]);
        }
        __syncthreads();
    }
#pragma unroll
    for (int mi = 0; mi < 2; mi++)
#pragma unroll
        for (int ni = 0; ni < 8; ni++) {
            int row = rowBase + warpRow + mi * 16 + g;
            int col = colBase + warpCol + ni * 8 + tg * 2;
            d_z[(size_t)row * 1536 + col]     = sigm(acc[mi][ni][0] + bias[col]);
            d_z[(size_t)row * 1536 + col + 1] = sigm(acc[mi][ni][1] + bias[col + 1]);
            d_z[(size_t)(row + 8) * 1536 + col]     = sigm(acc[mi][ni][2] + bias[col]);
            d_z[(size_t)(row + 8) * 1536 + col + 1] = sigm(acc[mi][ni][3] + bias[col + 1]);
        }
}

DEV void aggin_body(int ab, const float* __restrict__ x, const float* __restrict__ ss,
                    const float* __restrict__ rki, const float* __restrict__ rks,
                    uint32_t* sm4) {
    float* As = (float*)sm4;
    float* Bs = As + 1024;
    int tid = threadIdx.x;
    int n = ab / 32, yg = (ab / 2) % 16, xg = ab & 1;
    int rowBase = yg * 64, colBase = xg * 64;
    int r0 = (tid >> 4) * 4, c0 = (tid & 15) * 4;
    float acc[4][4] = {};
    for (int kt = 0; kt < 256; kt += 16) {
        for (int idx = tid; idx < 1024; idx += 256) {
            int kk = idx & 15, m = idx >> 4, kg = kt + kk, b = rowBase + m;
            As[kk * 64 + m] = (kg < 128) ? x[b * 128 + kg] : ss[n * 131072 + b * 128 + kg - 128];
            int cc = idx & 63, k2 = idx >> 6, kg2 = kt + k2, c = colBase + cc;
            Bs[k2 * 64 + cc] = (kg2 < 128) ? rki[n * 16384 + kg2 * 128 + c]
                                           : rks[n * 16384 + (kg2 - 128) * 128 + c];
        }
        __syncthreads();
#pragma unroll
        for (int k = 0; k < 16; k++) {
            float4 a = *(const float4*)&As[k * 64 + r0];
            float4 bb = *(const float4*)&Bs[k * 64 + c0];
            float av[4] = {a.x, a.y, a.z, a.w}, bv[4] = {bb.x, bb.y, bb.z, bb.w};
#pragma unroll
            for (int i = 0; i < 4; i++)
#pragma unroll
                for (int j = 0; j < 4; j++) acc[i][j] += av[i] * bv[j];
        }
        __syncthreads();
    }
#pragma unroll
    for (int i = 0; i < 4; i++)
#pragma unroll
        for (int j = 0; j < 4; j++)
            d_aggin[n * 131072 + (rowBase + r0 + i) * 128 + colBase + c0 + j] = acc[i][j];
}

DEV void packW_body(int pb, const float* __restrict__ bw, const float* __restrict__ sw) {
    int idx = pb * 256 + threadIdx.x;
    if (idx >= 3 * 1152 * 128) return;
    int n = idx / 147456, rem = idx - n * 147456;
    int k = rem >> 7, o = rem & 127;
    int f = k / 9, j = k - f * 9;
    d_subW[idx] = (j == 0) ? bw[n * 16384 + f * 128 + o]
                           : sw[n * 131072 + (f * 8 + j - 1) * 128 + o];
}

__global__ __launch_bounds__(256, 2) void k_mega(
    const float* __restrict__ x, const float* __restrict__ lng, const float* __restrict__ lnb,
    const float* __restrict__ wb, const float* __restrict__ ws,
    const float* __restrict__ skw, const float* __restrict__ skb,
    const float* __restrict__ h0, const float* __restrict__ W1, const float* __restrict__ W2,
    const float* __restrict__ bias,
    const float* __restrict__ ss, const float* __restrict__ rki, const float* __restrict__ rks,
    const float* __restrict__ bw, const float* __restrict__ sw) {
    extern __shared__ uint32_t sm4[];
    int bid = blockIdx.x;
    if (bid < 256)       mma_body(bid, x, lng, lnb, wb, ws, sm4);
    else if (bid < 1280) skip_body(bid - 256, x, skw, skb, sm4);
    else if (bid < 1376) z_body(bid - 1280, x, h0, W1, W2, bias, sm4);
    else if (bid < 1472) aggin_body(bid - 1376, x, ss, rki, rks, sm4);
    else                 packW_body(bid - 1472, bw, sw);
}

// =========================================================================
// K-MID: head (0..1023) + subexpand (1024..4095), 128 threads
// =========================================================================
DEV void head_body(int b, const float* g2g, const float* g2b,
                   const float* k2base, const float* k2spl,
                   const float* gw, const float* gb, const float* sw2, const float* sb,
                   const float* lg, const float* lb, float* sh) {
    int t = threadIdx.x;
    float v[4], S = 0.f, Q = 0.f;
#pragma unroll
    for (int m = 0; m < 4; m++) {
        float s = 0.f;
#pragma unroll
        for (int ks = 0; ks < 8; ks++)
            s += d_part[(size_t)ks * (B_ * U_) + b * 512 + t + 128 * m];
        v[m] = s;
        S += s; Q += s * s;
    }
    S = red128s(S, sh); Q = red128s(Q, sh);
    float mean = S / 512.f;
    float rstd = rsqrtf(Q / 512.f - mean * mean + 1e-3f);
    float a0 = 0.f, a1 = 0.f, a2 = 0.f;
#pragma unroll
    for (int m = 0; m < 4; m++) {
        int i = t + 128 * m;
        float xn = (v[m] - mean) * rstd * g2g[i] + g2b[i];
        float e[9];
        kan_expand(xn, e);
        a0 += e[0] * k2base[i * 3 + 0];
        a1 += e[0] * k2base[i * 3 + 1];
        a2 += e[0] * k2base[i * 3 + 2];
#pragma unroll
        for (int j = 0; j < 8; j++) {
            const float* sp = k2spl + (size_t)(i * 8 + j) * 3;
            a0 += e[1 + j] * sp[0];
            a1 += e[1 + j] * sp[1];
            a2 += e[1 + j] * sp[2];
        }
    }
    a0 = red128s(a0, sh); a1 = red128s(a1, sh); a2 = red128s(a2, sh);
    if (t == 0) {
        float h2[3] = {a0, a1, a2};
        float y[3];
#pragma unroll
        for (int o = 0; o < 3; o++) {
            float g1 = gb[o], s1 = sb[o];
#pragma unroll
            for (int p = 0; p < 3; p++) { g1 += h2[p] * gw[p * 3 + o]; s1 += h2[p] * sw2[p * 3 + o]; }
            y[o] = d_skip[b * 3 + o] + g1 * sigm(s1);
        }
        float m = (y[0] + y[1] + y[2]) * (1.f / 3.f);
        float var = ((y[0] - m) * (y[0] - m) + (y[1] - m) * (y[1] - m) + (y[2] - m) * (y[2] - m)) * (1.f / 3.f);
        float rs = rsqrtf(var + 1e-3f);
        float yn[3], mx = -1e30f;
#pragma unroll
        for (int o = 0; o < 3; o++) { yn[o] = (y[o] - m) * rs * lg[o] + lb[o]; mx = fmaxf(mx, yn[o]); }
        float e0 = __expf(yn[0] - mx), e1 = __expf(yn[1] - mx), e2 = __expf(yn[2] - mx);
        float inv = 1.f / (e0 + e1 + e2);
        d_sigw[b * 3 + 0] = e0 * inv;
        d_sigw[b * 3 + 1] = e1 * inv;
        d_sigw[b * 3 + 2] = e2 * inv;
    }
}

DEV void subexpand_body(int bx, const float* lg, const float* lb, float* sh) {
    int t = threadIdx.x;
    int n = bx >> 10;
    float v = d_aggin[bx * 128 + t];
    float S = red128s(v, sh), Q = red128s(v * v, sh);
    float mean = S * (1.f / 128.f);
    float rstd = rsqrtf(Q * (1.f / 128.f) - mean * mean + 1e-3f);
    float xn = (v - mean) * rstd * lg[n * 128 + t] + lb[n * 128 + t];
    float e[9];
    kan_expand(xn, e);
    size_t base = (size_t)bx * 1152 + t * 9;
#pragma unroll
    for (int j = 0; j < 9; j++) d_subE[base + j] = e[j];
}

__global__ __launch_bounds__(128) void k_mid(
    const float* __restrict__ g2g, const float* __restrict__ g2b,
    const float* __restrict__ k2base, const float* __restrict__ k2spl,
    const float* __restrict__ gw, const float* __restrict__ gb,
    const float* __restrict__ sw2, const float* __restrict__ sb,
    const float* __restrict__ lg, const float* __restrict__ lb,
    const float* __restrict__ slg, const float* __restrict__ slb) {
    __shared__ float sh[128];
    int bid = blockIdx.x;
    if (bid < 1024) head_body(bid, g2g, g2b, k2base, k2spl, gw, gb, sw2, sb, lg, lb, sh);
    else            subexpand_body(bid - 1024, slg, slb, sh);
}

// ---------- K8: sub GEMM via tf32 MMA, 64-row tiles ----------
__global__ __launch_bounds__(256) void k_subgemm(const float* __restrict__ ss,
                                                 const float* __restrict__ subk,
                                                 float* __restrict__ out_ss) {
    __shared__ uint32_t As4[64 * LDAZ];
    __shared__ uint32_t Bs4[32 * LDBZ];
    int tid = threadIdx.x, lane = tid & 31, wid = tid >> 5;
    int n = blockIdx.x, rowBase = blockIdx.y * 64;
    int warpRow = (wid & 1) * 32, warpCol = (wid >> 1) * 32;
    int g = lane >> 2, tg = lane & 3;
    int rsel = wid, n4 = lane * 4;
    int arow = tid >> 2, aseg = (tid & 3) * 8;
    const float* E = d_subE + (size_t)n * B_ * 1152;
    const float* W = d_subW + (size_t)n * 147456;

    float acc[2][4][4];
#pragma unroll
    for (int mi = 0; mi < 2; mi++)
#pragma unroll
        for (int ni = 0; ni < 4; ni++)
#pragma unroll
            for (int q = 0; q < 4; q++) acc[mi][ni][q] = 0.f;

    for (int kt = 0; kt < 1152; kt += 32) {
        const float* src = E + (size_t)(rowBase + arow) * 1152 + kt + aseg;
#pragma unroll
        for (int q = 0; q < 2; q++) {
            float4 v = *(const float4*)(src + q * 4);
            uint4 w;
            w.x = f2tf(v.x); w.y = f2tf(v.y); w.z = f2tf(v.z); w.w = f2tf(v.w);
            *(uint4*)&As4[arow * LDAZ + aseg + q * 4] = w;
        }
#pragma unroll
        for (int i = 0; i < 4; i++) {
            int kl = i * 8 + rsel;
            float4 v = *(const float4*)(W + (size_t)(kt + kl) * 128 + n4);
            uint4 w;
            w.x = f2tf(v.x); w.y = f2tf(v.y); w.z = f2tf(v.z); w.w = f2tf(v.w);
            *(uint4*)&Bs4[kl * LDBZ + n4] = w;
        }
        __syncthreads();
#pragma unroll
        for (int ks2 = 0; ks2 < 4; ks2++) {
            int k0 = ks2 * 8;
            uint32_t aF[2][4];
#pragma unroll
            for (int mi = 0; mi < 2; mi++) {
                int r = warpRow + mi * 16;
                aF[mi][0] = As4[(r + g) * LDAZ + k0 + tg];
                aF[mi][1] = As4[(r + 8 + g) * LDAZ + k0 + tg];
                aF[mi][2] = As4[(r + g) * LDAZ + k0 + tg + 4];
                aF[mi][3] = As4[(r + 8 + g) * LDAZ + k0 + tg + 4];
            }
            uint32_t bF[4][2];
#pragma unroll
            for (int ni = 0; ni < 4; ni++) {
                int c = warpCol + ni * 8 + g;
                bF[ni][0] = Bs4[(k0 + tg) * LDBZ + c];
                bF[ni][1] = Bs4[(k0 + tg + 4) * LDBZ + c];
            }
#pragma unroll
            for (int mi = 0; mi < 2; mi++)
#pragma unroll
                for (int ni = 0; ni < 4; ni++)
                    mma_tf32(acc[mi][ni], aF[mi], bF[ni]);
        }
        __syncthreads();
    }
#pragma unroll
    for (int mi = 0; mi < 2; mi++)
#pragma unroll
        for (int ni = 0; ni < 4; ni++) {
            int col = warpCol + ni * 8 + tg * 2;
            float rkh0 = subk[n * 256 + col], rkh1 = subk[n * 256 + col + 1];
            float rkx0 = subk[n * 256 + 128 + col], rkx1 = subk[n * 256 + 128 + col + 1];
#pragma unroll
            for (int h = 0; h < 2; h++) {
                int row = rowBase + warpRow + mi * 16 + g + h * 8;
                float sgw = d_sigw[row * 3 + n];
                float v0 = acc[mi][ni][h * 2 + 0] * sgw;
                float v1 = acc[mi][ni][h * 2 + 1] * sgw;
                d_agg[row * 384 + n * 128 + col] = v0;
                d_agg[row * 384 + n * 128 + col + 1] = v1;
                size_t so = (size_t)n * 131072 + (size_t)row * 128 + col;
                out_ss[so]     = rkh0 * v0 + ss[so] * rkx0;
                out_ss[so + 1] = rkh1 * v1 + ss[so + 1] * rkx1;
            }
        }
}

// ---------- K9: x_o GEMM via tf32 MMA, 64-row tiles ----------
__global__ __launch_bounds__(256) void k_final(const float* __restrict__ aw, const float* __restrict__ ab,
                                               const float* __restrict__ c0p, float* __restrict__ out) {
    __shared__ uint32_t As4[64 * LDAZ];
    __shared__ uint32_t Bs4[32 * LDBZ];
    int tid = threadIdx.x, lane = tid & 31, wid = tid >> 5;
    int colBase = blockIdx.x * 128, rowBase = blockIdx.y * 64;
    int warpRow = (wid & 1) * 32, warpCol = (wid >> 1) * 32;
    int g = lane >> 2, tg = lane & 3;
    int rsel = wid, n4 = lane * 4;
    int arow = tid >> 2, aseg = (tid & 3) * 8;

    float acc[2][4][4];
#pragma unroll
    for (int mi = 0; mi < 2; mi++)
#pragma unroll
        for (int ni = 0; ni < 4; ni++)
#pragma unroll
            for (int q = 0; q < 4; q++) acc[mi][ni][q] = 0.f;

    for (int kt = 0; kt < 384; kt += 32) {
        const float* src = d_agg + (size_t)(rowBase + arow) * 384 + kt + aseg;
#pragma unroll
        for (int q = 0; q < 2; q++) {
            float4 v = *(const float4*)(src + q * 4);
            uint4 w;
            w.x = f2tf(v.x); w.y = f2tf(v.y); w.z = f2tf(v.z); w.w = f2tf(v.w);
            *(uint4*)&As4[arow * LDAZ + aseg + q * 4] = w;
        }
#pragma unroll
        for (int i = 0; i < 4; i++) {
            int kl = i * 8 + rsel;
            float4 v = *(const float4*)(aw + (size_t)(kt + kl) * 512 + colBase + n4);
            uint4 w;
            w.x = f2tf(v.x); w.y = f2tf(v.y); w.z = f2tf(v.z); w.w = f2tf(v.w);
            *(uint4*)&Bs4[kl * LDBZ + n4] = w;
        }
        __syncthreads();
#pragma unroll
        for (int ks2 = 0; ks2 < 4; ks2++) {
            int k0 = ks2 * 8;
            uint32_t aF[2][4];
#pragma unroll
            for (int mi = 0; mi < 2; mi++) {
                int r = warpRow + mi * 16;
                aF[mi][0] = As4[(r + g) * LDAZ + k0 + tg];
                aF[mi][1] = As4[(r + 8 + g) * LDAZ + k0 + tg];
                aF[mi][2] = As4[(r + g) * LDAZ + k0 + tg + 4];
                aF[mi][3] = As4[(r + 8 + g) * LDAZ + k0 + tg + 4];
            }
            uint32_t bF[4][2];
#pragma unroll
            for (int ni = 0; ni < 4; ni++) {
                int c = warpCol + ni * 8 + g;
                bF[ni][0] = Bs4[(k0 + tg) * LDBZ + c];
                bF[ni][1] = Bs4[(k0 + tg + 4) * LDBZ + c];
            }
#pragma unroll
            for (int mi = 0; mi < 2; mi++)
#pragma unroll
                for (int ni = 0; ni < 4; ni++)
                    mma_tf32(acc[mi][ni], aF[mi], bF[ni]);
        }
        __syncthreads();
    }
#pragma unroll
    for (int mi = 0; mi < 2; mi++)
#pragma unroll
        for (int ni = 0; ni < 4; ni++) {
            int col = colBase + warpCol + ni * 8 + tg * 2;
#pragma unroll
            for (int h = 0; h < 2; h++) {
                int row = rowBase + warpRow + mi * 16 + g + h * 8;
#pragma unroll
                for (int c = 0; c < 2; c++) {
                    int cc = col + c;
                    float xo = sigm(acc[mi][ni][h * 2 + c] + ab[cc]);
                    float zi = d_z[(size_t)row * 1536 + cc];
                    float zf = d_z[(size_t)row * 1536 + 512 + cc];
                    float zc = d_z[(size_t)row * 1536 + 1024 + cc];
                    float cv = zf * c0p[(size_t)row * 512 + cc] + zi * zc;
                    out[(size_t)row * 512 + cc] = xo * tanhf(cv);
                    out[B_ * U_ + (size_t)row * 512 + cc] = cv;
                }
            }
        }
}

// ---------- launch ----------
extern "C" void kernel_launch(void* const* d_in, const int* in_sizes, int n_in,
                              void* d_out, int out_size) {
    const float* inputs   = (const float*)d_in[0];
    const float* h0       = (const float*)d_in[1];
    const float* c0       = (const float*)d_in[2];
    const float* sub_st   = (const float*)d_in[3];
    const float* kern     = (const float*)d_in[4];
    const float* rkern    = (const float*)d_in[5];
    const float* bias     = (const float*)d_in[6];
    const float* sub_k    = (const float*)d_in[7];
    const float* sub_rki  = (const float*)d_in[8];
    const float* sub_rks  = (const float*)d_in[9];
    const float* agg_w    = (const float*)d_in[10];
    const float* agg_b    = (const float*)d_in[11];
    const float* sub_lng  = (const float*)d_in[12];
    const float* sub_lnb  = (const float*)d_in[13];
    const float* sub_bw   = (const float*)d_in[14];
    const float* sub_sw   = (const float*)d_in[15];
    const float* g_skw    = (const float*)d_in[16];
    const float* g_skb    = (const float*)d_in[17];
    const float* k1_lng   = (const float*)d_in[18];
    const float* k1_lnb   = (const float*)d_in[19];
    const float* k1_base  = (const float*)d_in[20];
    const float* k1_spl   = (const float*)d_in[21];
    const float* k2_lng   = (const float*)d_in[22];
    const float* k2_lnb   = (const float*)d_in[23];
    const float* k2_base  = (const float*)d_in[24];
    const float* k2_spl   = (const float*)d_in[25];
    const float* gw       = (const float*)d_in[26];
    const float* gb       = (const float*)d_in[27];
    const float* sw       = (const float*)d_in[28];
    const float* sb       = (const float*)d_in[29];
    const float* lg       = (const float*)d_in[30];
    const float* lb       = (const float*)d_in[31];
    float* out = (float*)d_out;

    static bool attr_set = false;
    if (!attr_set) {
        cudaFuncSetAttribute(k_mega, cudaFuncAttributeMaxDynamicSharedMemorySize, SM_MEGA);
        attr_set = true;
    }

    k_mega<<<3200, 256, SM_MEGA>>>(inputs, k1_lng, k1_lnb, k1_base, k1_spl,
                                   g_skw, g_skb, h0, kern, rkern, bias,
                                   sub_st, sub_rki, sub_rks, sub_bw, sub_sw);
    k_mid<<<4096, 128>>>(k2_lng, k2_lnb, k2_base, k2_spl, gw, gb, sw, sb, lg, lb,
                         sub_lng, sub_lnb);
    k_subgemm<<<dim3(3, 16), 256>>>(sub_st, sub_k, out + 2 * B_ * U_);
    k_final<<<dim3(4, 16), 256>>>(agg_w, agg_b, c0, out);
}

// round 16
// speedup vs baseline: 1.0946x; 1.0946x over previous
#include <cuda_runtime.h>
#include <cuda_bf16.h>
#include <stdint.h>

#define DEV __device__ __forceinline__
typedef unsigned long long ull;

#define B_ 1024
#define U_ 512
#define SIGD 16512

// ---------- scratch ----------
__device__ float d_skip[B_ * 3];
__device__ float d_sigw[B_ * 3];
__device__ __align__(16) float d_z[B_ * 1536];
__device__ __align__(16) float d_aggin[3 * B_ * 128];
__device__ __align__(16) float d_subE[3 * B_ * 1152];
__device__ __align__(16) float d_subW[3 * 1152 * 128];
__device__ __align__(16) float d_agg[B_ * 384];
__device__ __align__(16) float d_part[8 * B_ * U_];

// ---------- helpers ----------
DEV float sigm(float x) { return 1.f / (1.f + __expf(-x)); }
DEV uint32_t f2tf(float f) {
    uint32_t r;
    asm("cvt.rna.tf32.f32 %0,%1;" : "=r"(r) : "f"(f));
    return r;
}
DEV void mma_tf32(float acc[4], const uint32_t a[4], const uint32_t b[2]) {
    asm volatile(
        "mma.sync.aligned.m16n8k8.row.col.f32.tf32.tf32.f32 "
        "{%0,%1,%2,%3},{%4,%5,%6,%7},{%8,%9},{%0,%1,%2,%3};"
        : "+f"(acc[0]), "+f"(acc[1]), "+f"(acc[2]), "+f"(acc[3])
        : "r"(a[0]), "r"(a[1]), "r"(a[2]), "r"(a[3]), "r"(b[0]), "r"(b[1]));
}

DEV void kan_expand(float xn, float e[9]) {
    e[0] = xn * sigm(xn);
#pragma unroll
    for (int j = 1; j < 9; j++) e[j] = 0.f;
    float tp = (xn + 2.2f) * 2.5f;
    float tf = floorf(tp);
    if (tf >= 0.f && tf <= 10.f) {
        int t = (int)tf;
        float u = tp - tf, u2 = u * u, u3 = u2 * u, omu = 1.f - u;
        float v0 = omu * omu * omu * (1.f / 6.f);
        float v1 = (3.f * u3 - 6.f * u2 + 4.f) * (1.f / 6.f);
        float v2 = (-3.f * u3 + 3.f * u2 + 3.f * u + 1.f) * (1.f / 6.f);
        float v3 = u3 * (1.f / 6.f);
        if (t >= 3)           e[t - 2] = v0;
        if (t >= 2 && t <= 9) e[t - 1] = v1;
        if (t >= 1 && t <= 8) e[t]     = v2;
        if (t <= 7)           e[t + 1] = v3;
    }
}

DEV float red128s(float v, float* sh) {
    int t = threadIdx.x;
    sh[t] = v; __syncthreads();
#pragma unroll
    for (int s = 64; s > 0; s >>= 1) { if (t < s) sh[t] += sh[t + s]; __syncthreads(); }
    float r = sh[0]; __syncthreads();
    return r;
}
DEV float red256s(float v, float* sh) {
    int t = threadIdx.x;
    sh[t] = v; __syncthreads();
#pragma unroll
    for (int s = 128; s > 0; s >>= 1) { if (t < s) sh[t] += sh[t + s]; __syncthreads(); }
    float r = sh[0]; __syncthreads();
    return r;
}

// =========================================================================
// K-MEGA: MMA (0..255) + skip (256..1279) + z (1280..1375)
//         + aggin (1376..1471) + packW (1472..3199)
// =========================================================================
#define LDA4 76
#define LDB4 136
#define SM_MEGA (23904 * 4)   // 95616 bytes

DEV void mma_body(int bid, const float* __restrict__ x,
                  const float* __restrict__ lng, const float* __restrict__ lnb,
                  const float* __restrict__ wb, const float* __restrict__ ws,
                  uint32_t* sm4) {
    uint32_t* As4 = sm4;
    uint32_t* Bs4 = sm4 + 9728;
    float* lngS = (float*)(sm4 + 19520);
    float* lnbS = (float*)(sm4 + 21584);
    float* mus  = (float*)(sm4 + 23648);
    float* rss  = (float*)(sm4 + 23776);

    int tid = threadIdx.x, lane = tid & 31, wid = tid >> 5;
    int ks = bid & 7, mg = (bid >> 3) & 7, ng = bid >> 6;
    int rowBase = mg * 128, colBase = ng * 128;
    int warpRow = (wid & 3) * 32, warpCol = (wid >> 2) * 64;
    int g = lane >> 2, tg = lane & 3;
    int rsel = wid, n4 = lane * 4;
    int ksBase = ks * 2064;

#pragma unroll 1
    for (int rr = 0; rr < 16; rr++) {
        int row = wid * 16 + rr;
        float4 v = *(const float4*)(x + (size_t)(rowBase + row) * 128 + lane * 4);
        float s = v.x + v.y + v.z + v.w;
        float q = v.x * v.x + v.y * v.y + v.z * v.z + v.w * v.w;
#pragma unroll
        for (int off = 16; off > 0; off >>= 1) {
            s += __shfl_xor_sync(0xFFFFFFFFu, s, off);
            q += __shfl_xor_sync(0xFFFFFFFFu, q, off);
        }
        if (lane == 0) {
            float mean = (s + 0.5f * s * s) / (float)SIGD;
            float m2 = (q + 0.25f * q * q) / (float)SIGD;
            mus[row] = mean;
            rss[row] = rsqrtf(m2 - mean * mean + 1e-3f);
        }
    }
    for (int i = tid; i < 2064; i += 256) {
        lngS[i] = lng[ksBase + i];
        lnbS[i] = lnb[ksBase + i];
    }
    __syncthreads();

    float acc[2][8][4];
#pragma unroll
    for (int mi = 0; mi < 2; mi++)
#pragma unroll
        for (int ni = 0; ni < 8; ni++)
#pragma unroll
            for (int q = 0; q < 4; q++) acc[mi][ni][q] = 0.f;

    for (int ch = 0; ch < 258; ch++) {
        int f0 = ksBase + ch * 8;
        int l0 = ch * 8;
#pragma unroll
        for (int p = 0; p < 4; p++) {
            int task = tid + p * 256;
            int fl = task & 7, row = task >> 3;
            int fg = f0 + fl;
            const float* xr = x + (size_t)(rowBase + row) * 128;
            float val;
            if (fg < 128) val = __ldg(xr + fg);
            else {
                int q = fg - 128;
                val = 0.5f * __ldg(xr + (q >> 7)) * __ldg(xr + (q & 127));
            }
            float xn = (val - mus[row]) * rss[row] * lngS[l0 + fl] + lnbS[l0 + fl];
            float e[9];
            kan_expand(xn, e);
            int off = row * LDA4 + fl * 9;
#pragma unroll
            for (int j = 0; j < 9; j++) As4[off + j] = f2tf(e[j]);
        }
#pragma unroll
        for (int i = 0; i < 9; i++) {
            int kl = i * 8 + rsel;
            int kg = f0 * 9 + kl;
            int f = kg / 9, jj = kg - f * 9;
            const float* p = (jj == 0) ? wb + (size_t)f * 512
                                       : ws + ((size_t)f * 8 + (jj - 1)) * 512;
            float4 v = *(const float4*)(p + colBase + n4);
            uint4 w;
            w.x = f2tf(v.x); w.y = f2tf(v.y); w.z = f2tf(v.z); w.w = f2tf(v.w);
            *(uint4*)&Bs4[kl * LDB4 + n4] = w;
        }
        __syncthreads();
#pragma unroll 3
        for (int ks2 = 0; ks2 < 9; ks2++) {
            int k0 = ks2 * 8;
            uint32_t aF[2][4];
#pragma unroll
            for (int mi = 0; mi < 2; mi++) {
                int r = warpRow + mi * 16;
                aF[mi][0] = As4[(r + g) * LDA4 + k0 + tg];
                aF[mi][1] = As4[(r + 8 + g) * LDA4 + k0 + tg];
                aF[mi][2] = As4[(r + g) * LDA4 + k0 + tg + 4];
                aF[mi][3] = As4[(r + 8 + g) * LDA4 + k0 + tg + 4];
            }
            uint32_t bF[8][2];
#pragma unroll
            for (int ni = 0; ni < 8; ni++) {
                int c = warpCol + ni * 8 + g;
                bF[ni][0] = Bs4[(k0 + tg) * LDB4 + c];
                bF[ni][1] = Bs4[(k0 + tg + 4) * LDB4 + c];
            }
#pragma unroll
            for (int mi = 0; mi < 2; mi++)
#pragma unroll
                for (int ni = 0; ni < 8; ni++)
                    mma_tf32(acc[mi][ni], aF[mi], bF[ni]);
        }
        __syncthreads();
    }
    float* dp = d_part + (size_t)ks * (B_ * U_);
#pragma unroll
    for (int mi = 0; mi < 2; mi++)
#pragma unroll
        for (int ni = 0; ni < 8; ni++) {
            int row = rowBase + warpRow + mi * 16 + g;
            int col = colBase + warpCol + ni * 8 + tg * 2;
            *(float2*)&dp[(size_t)row * 512 + col] = make_float2(acc[mi][ni][0], acc[mi][ni][1]);
            *(float2*)&dp[(size_t)(row + 8) * 512 + col] = make_float2(acc[mi][ni][2], acc[mi][ni][3]);
        }
}

DEV void skip_body(int b, const float* __restrict__ x,
                   const float* __restrict__ skw, const float* __restrict__ skb,
                   uint32_t* sm4) {
    float* xs = (float*)sm4;
    float* sh = xs + 128;
    int t = threadIdx.x;
    if (t < 128) xs[t] = x[b * 128 + t];
    __syncthreads();
    float a0 = 0.f, a1 = 0.f, a2 = 0.f;
    for (int i = t; i < SIGD; i += 256) {
        float sv = (i < 128) ? xs[i] : 0.5f * xs[(i - 128) >> 7] * xs[(i - 128) & 127];
        a0 += sv * skw[i * 3 + 0];
        a1 += sv * skw[i * 3 + 1];
        a2 += sv * skw[i * 3 + 2];
    }
    a0 = red256s(a0, sh); a1 = red256s(a1, sh); a2 = red256s(a2, sh);
    if (t == 0) {
        d_skip[b * 3 + 0] = a0 + skb[0];
        d_skip[b * 3 + 1] = a1 + skb[1];
        d_skip[b * 3 + 2] = a2 + skb[2];
    }
}

#define LDAZ 36
#define LDBZ 136
DEV void z_body(int zb, const float* __restrict__ x, const float* __restrict__ h0,
                const float* __restrict__ W1, const float* __restrict__ W2,
                const float* __restrict__ bias, uint32_t* sm4) {
    uint32_t* As4 = sm4;
    uint32_t* Bs4 = sm4 + 4608;
    int tid = threadIdx.x, lane = tid & 31, wid = tid >> 5;
    int colBase = (zb % 12) * 128, rowBase = (zb / 12) * 128;
    int warpRow = (wid & 3) * 32, warpCol = (wid >> 2) * 64;
    int g = lane >> 2, tg = lane & 3;
    int rsel = wid, n4 = lane * 4;
    int arow = tid >> 1, ahalf = tid & 1;

    float acc[2][8][4];
#pragma unroll
    for (int mi = 0; mi < 2; mi++)
#pragma unroll
        for (int ni = 0; ni < 8; ni++)
#pragma unroll
            for (int q = 0; q < 4; q++) acc[mi][ni][q] = 0.f;

    for (int kt = 0; kt < 640; kt += 32) {
        const float* src = (kt < 128) ? x + (size_t)(rowBase + arow) * 128 + kt + ahalf * 16
                                      : h0 + (size_t)(rowBase + arow) * 512 + (kt - 128) + ahalf * 16;
#pragma unroll
        for (int q = 0; q < 4; q++) {
            float4 v = *(const float4*)(src + q * 4);
            uint4 w;
            w.x = f2tf(v.x); w.y = f2tf(v.y); w.z = f2tf(v.z); w.w = f2tf(v.w);
            *(uint4*)&As4[arow * LDAZ + ahalf * 16 + q * 4] = w;
        }
#pragma unroll
        for (int i = 0; i < 4; i++) {
            int kl = i * 8 + rsel;
            int kg = kt + kl;
            const float* p = (kg < 128) ? W1 + (size_t)kg * 1536 + colBase + n4
                                        : W2 + (size_t)(kg - 128) * 1536 + colBase + n4;
            float4 v = *(const float4*)p;
            uint4 w;
            w.x = f2tf(v.x); w.y = f2tf(v.y); w.z = f2tf(v.z); w.w = f2tf(v.w);
            *(uint4*)&Bs4[kl * LDBZ + n4] = w;
        }
        __syncthreads();
#pragma unroll
        for (int ks2 = 0; ks2 < 4; ks2++) {
            int k0 = ks2 * 8;
            uint32_t aF[2][4];
#pragma unroll
            for (int mi = 0; mi < 2; mi++) {
                int r = warpRow + mi * 16;
                aF[mi][0] = As4[(r + g) * LDAZ + k0 + tg];
                aF[mi][1] = As4[(r + 8 + g) * LDAZ + k0 + tg];
                aF[mi][2] = As4[(r + g) * LDAZ + k0 + tg + 4];
                aF[mi][3] = As4[(r + 8 + g) * LDAZ + k0 + tg + 4];
            }
            uint32_t bF[8][2];
#pragma unroll
            for (int ni = 0; ni < 8; ni++) {
                int c = warpCol + ni * 8 + g;
                bF[ni][0] = Bs4[(k0 + tg) * LDBZ + c];
                bF[ni][1] = Bs4[(k0 + tg + 4) * LDBZ + c];
            }
#pragma unroll
            for (int mi = 0; mi < 2; mi++)
#pragma unroll
                for (int ni = 0; ni < 8; ni++)
                    mma_tf32(acc[mi][ni], aF[mi], bF[ni]);
        }
        __syncthreads();
    }
#pragma unroll
    for (int mi = 0; mi < 2; mi++)
#pragma unroll
        for (int ni = 0; ni < 8; ni++) {
            int row = rowBase + warpRow + mi * 16 + g;
            int col = colBase + warpCol + ni * 8 + tg * 2;
            d_z[(size_t)row * 1536 + col]     = sigm(acc[mi][ni][0] + bias[col]);
            d_z[(size_t)row * 1536 + col + 1] = sigm(acc[mi][ni][1] + bias[col + 1]);
            d_z[(size_t)(row + 8) * 1536 + col]     = sigm(acc[mi][ni][2] + bias[col]);
            d_z[(size_t)(row + 8) * 1536 + col + 1] = sigm(acc[mi][ni][3] + bias[col + 1]);
        }
}

DEV void aggin_body(int ab, const float* __restrict__ x, const float* __restrict__ ss,
                    const float* __restrict__ rki, const float* __restrict__ rks,
                    uint32_t* sm4) {
    float* As = (float*)sm4;
    float* Bs = As + 1024;
    int tid = threadIdx.x;
    int n = ab / 32, yg = (ab / 2) % 16, xg = ab & 1;
    int rowBase = yg * 64, colBase = xg * 64;
    int r0 = (tid >> 4) * 4, c0 = (tid & 15) * 4;
    float acc[4][4] = {};
    for (int kt = 0; kt < 256; kt += 16) {
        for (int idx = tid; idx < 1024; idx += 256) {
            int kk = idx & 15, m = idx >> 4, kg = kt + kk, b = rowBase + m;
            As[kk * 64 + m] = (kg < 128) ? x[b * 128 + kg] : ss[n * 131072 + b * 128 + kg - 128];
            int cc = idx & 63, k2 = idx >> 6, kg2 = kt + k2, c = colBase + cc;
            Bs[k2 * 64 + cc] = (kg2 < 128) ? rki[n * 16384 + kg2 * 128 + c]
                                           : rks[n * 16384 + (kg2 - 128) * 128 + c];
        }
        __syncthreads();
#pragma unroll
        for (int k = 0; k < 16; k++) {
            float4 a = *(const float4*)&As[k * 64 + r0];
            float4 bb = *(const float4*)&Bs[k * 64 + c0];
            float av[4] = {a.x, a.y, a.z, a.w}, bv[4] = {bb.x, bb.y, bb.z, bb.w};
#pragma unroll
            for (int i = 0; i < 4; i++)
#pragma unroll
                for (int j = 0; j < 4; j++) acc[i][j] += av[i] * bv[j];
        }
        __syncthreads();
    }
#pragma unroll
    for (int i = 0; i < 4; i++)
#pragma unroll
        for (int j = 0; j < 4; j++)
            d_aggin[n * 131072 + (rowBase + r0 + i) * 128 + colBase + c0 + j] = acc[i][j];
}

DEV void packW_body(int pb, const float* __restrict__ bw, const float* __restrict__ sw) {
    int idx = pb * 256 + threadIdx.x;
    if (idx >= 3 * 1152 * 128) return;
    int n = idx / 147456, rem = idx - n * 147456;
    int k = rem >> 7, o = rem & 127;
    int f = k / 9, j = k - f * 9;
    d_subW[idx] = (j == 0) ? bw[n * 16384 + f * 128 + o]
                           : sw[n * 131072 + (f * 8 + j - 1) * 128 + o];
}

__global__ __launch_bounds__(256, 2) void k_mega(
    const float* __restrict__ x, const float* __restrict__ lng, const float* __restrict__ lnb,
    const float* __restrict__ wb, const float* __restrict__ ws,
    const float* __restrict__ skw, const float* __restrict__ skb,
    const float* __restrict__ h0, const float* __restrict__ W1, const float* __restrict__ W2,
    const float* __restrict__ bias,
    const float* __restrict__ ss, const float* __restrict__ rki, const float* __restrict__ rks,
    const float* __restrict__ bw, const float* __restrict__ sw) {
    extern __shared__ uint32_t sm4[];
    int bid = blockIdx.x;
    if (bid < 256)       mma_body(bid, x, lng, lnb, wb, ws, sm4);
    else if (bid < 1280) skip_body(bid - 256, x, skw, skb, sm4);
    else if (bid < 1376) z_body(bid - 1280, x, h0, W1, W2, bias, sm4);
    else if (bid < 1472) aggin_body(bid - 1376, x, ss, rki, rks, sm4);
    else                 packW_body(bid - 1472, bw, sw);
}

// =========================================================================
// K-MID: head (0..1023) + subexpand (1024..4095), 128 threads
// =========================================================================
DEV void head_body(int b, const float* g2g, const float* g2b,
                   const float* k2base, const float* k2spl,
                   const float* gw, const float* gb, const float* sw2, const float* sb,
                   const float* lg, const float* lb, float* sh) {
    int t = threadIdx.x;
    float v[4], S = 0.f, Q = 0.f;
#pragma unroll
    for (int m = 0; m < 4; m++) {
        float s = 0.f;
#pragma unroll
        for (int ks = 0; ks < 8; ks++)
            s += d_part[(size_t)ks * (B_ * U_) + b * 512 + t + 128 * m];
        v[m] = s;
        S += s; Q += s * s;
    }
    S = red128s(S, sh); Q = red128s(Q, sh);
    float mean = S / 512.f;
    float rstd = rsqrtf(Q / 512.f - mean * mean + 1e-3f);
    float a0 = 0.f, a1 = 0.f, a2 = 0.f;
#pragma unroll
    for (int m = 0; m < 4; m++) {
        int i = t + 128 * m;
        float xn = (v[m] - mean) * rstd * g2g[i] + g2b[i];
        float e[9];
        kan_expand(xn, e);
        a0 += e[0] * k2base[i * 3 + 0];
        a1 += e[0] * k2base[i * 3 + 1];
        a2 += e[0] * k2base[i * 3 + 2];
#pragma unroll
        for (int j = 0; j < 8; j++) {
            const float* sp = k2spl + (size_t)(i * 8 + j) * 3;
            a0 += e[1 + j] * sp[0];
            a1 += e[1 + j] * sp[1];
            a2 += e[1 + j] * sp[2];
        }
    }
    a0 = red128s(a0, sh); a1 = red128s(a1, sh); a2 = red128s(a2, sh);
    if (t == 0) {
        float h2[3] = {a0, a1, a2};
        float y[3];
#pragma unroll
        for (int o = 0; o < 3; o++) {
            float g1 = gb[o], s1 = sb[o];
#pragma unroll
            for (int p = 0; p < 3; p++) { g1 += h2[p] * gw[p * 3 + o]; s1 += h2[p] * sw2[p * 3 + o]; }
            y[o] = d_skip[b * 3 + o] + g1 * sigm(s1);
        }
        float m = (y[0] + y[1] + y[2]) * (1.f / 3.f);
        float var = ((y[0] - m) * (y[0] - m) + (y[1] - m) * (y[1] - m) + (y[2] - m) * (y[2] - m)) * (1.f / 3.f);
        float rs = rsqrtf(var + 1e-3f);
        float yn[3], mx = -1e30f;
#pragma unroll
        for (int o = 0; o < 3; o++) { yn[o] = (y[o] - m) * rs * lg[o] + lb[o]; mx = fmaxf(mx, yn[o]); }
        float e0 = __expf(yn[0] - mx), e1 = __expf(yn[1] - mx), e2 = __expf(yn[2] - mx);
        float inv = 1.f / (e0 + e1 + e2);
        d_sigw[b * 3 + 0] = e0 * inv;
        d_sigw[b * 3 + 1] = e1 * inv;
        d_sigw[b * 3 + 2] = e2 * inv;
    }
}

DEV void subexpand_body(int bx, const float* lg, const float* lb, float* sh) {
    int t = threadIdx.x;
    int n = bx >> 10;
    float v = d_aggin[bx * 128 + t];
    float S = red128s(v, sh), Q = red128s(v * v, sh);
    float mean = S * (1.f / 128.f);
    float rstd = rsqrtf(Q * (1.f / 128.f) - mean * mean + 1e-3f);
    float xn = (v - mean) * rstd * lg[n * 128 + t] + lb[n * 128 + t];
    float e[9];
    kan_expand(xn, e);
    size_t base = (size_t)bx * 1152 + t * 9;
#pragma unroll
    for (int j = 0; j < 9; j++) d_subE[base + j] = e[j];
}

__global__ __launch_bounds__(128) void k_mid(
    const float* __restrict__ g2g, const float* __restrict__ g2b,
    const float* __restrict__ k2base, const float* __restrict__ k2spl,
    const float* __restrict__ gw, const float* __restrict__ gb,
    const float* __restrict__ sw2, const float* __restrict__ sb,
    const float* __restrict__ lg, const float* __restrict__ lb,
    const float* __restrict__ slg, const float* __restrict__ slb) {
    __shared__ float sh[128];
    int bid = blockIdx.x;
    if (bid < 1024) head_body(bid, g2g, g2b, k2base, k2spl, gw, gb, sw2, sb, lg, lb, sh);
    else            subexpand_body(bid - 1024, slg, slb, sh);
}

// ---------- K8: sub GEMM via tf32 MMA, 64-row tiles ----------
__global__ __launch_bounds__(256) void k_subgemm(const float* __restrict__ ss,
                                                 const float* __restrict__ subk,
                                                 float* __restrict__ out_ss) {
    __shared__ uint32_t As4[64 * LDAZ];
    __shared__ uint32_t Bs4[32 * LDBZ];
    int tid = threadIdx.x, lane = tid & 31, wid = tid >> 5;
    int n = blockIdx.x, rowBase = blockIdx.y * 64;
    int warpRow = (wid & 1) * 32, warpCol = (wid >> 1) * 32;
    int g = lane >> 2, tg = lane & 3;
    int rsel = wid, n4 = lane * 4;
    int arow = tid >> 2, aseg = (tid & 3) * 8;
    const float* E = d_subE + (size_t)n * B_ * 1152;
    const float* W = d_subW + (size_t)n * 147456;

    float acc[2][4][4];
#pragma unroll
    for (int mi = 0; mi < 2; mi++)
#pragma unroll
        for (int ni = 0; ni < 4; ni++)
#pragma unroll
            for (int q = 0; q < 4; q++) acc[mi][ni][q] = 0.f;

    for (int kt = 0; kt < 1152; kt += 32) {
        const float* src = E + (size_t)(rowBase + arow) * 1152 + kt + aseg;
#pragma unroll
        for (int q = 0; q < 2; q++) {
            float4 v = *(const float4*)(src + q * 4);
            uint4 w;
            w.x = f2tf(v.x); w.y = f2tf(v.y); w.z = f2tf(v.z); w.w = f2tf(v.w);
            *(uint4*)&As4[arow * LDAZ + aseg + q * 4] = w;
        }
#pragma unroll
        for (int i = 0; i < 4; i++) {
            int kl = i * 8 + rsel;
            float4 v = *(const float4*)(W + (size_t)(kt + kl) * 128 + n4);
            uint4 w;
            w.x = f2tf(v.x); w.y = f2tf(v.y); w.z = f2tf(v.z); w.w = f2tf(v.w);
            *(uint4*)&Bs4[kl * LDBZ + n4] = w;
        }
        __syncthreads();
#pragma unroll
        for (int ks2 = 0; ks2 < 4; ks2++) {
            int k0 = ks2 * 8;
            uint32_t aF[2][4];
#pragma unroll
            for (int mi = 0; mi < 2; mi++) {
                int r = warpRow + mi * 16;
                aF[mi][0] = As4[(r + g) * LDAZ + k0 + tg];
                aF[mi][1] = As4[(r + 8 + g) * LDAZ + k0 + tg];
                aF[mi][2] = As4[(r + g) * LDAZ + k0 + tg + 4];
                aF[mi][3] = As4[(r + 8 + g) * LDAZ + k0 + tg + 4];
            }
            uint32_t bF[4][2];
#pragma unroll
            for (int ni = 0; ni < 4; ni++) {
                int c = warpCol + ni * 8 + g;
                bF[ni][0] = Bs4[(k0 + tg) * LDBZ + c];
                bF[ni][1] = Bs4[(k0 + tg + 4) * LDBZ + c];
            }
#pragma unroll
            for (int mi = 0; mi < 2; mi++)
#pragma unroll
                for (int ni = 0; ni < 4; ni++)
                    mma_tf32(acc[mi][ni], aF[mi], bF[ni]);
        }
        __syncthreads();
    }
#pragma unroll
    for (int mi = 0; mi < 2; mi++)
#pragma unroll
        for (int ni = 0; ni < 4; ni++) {
            int col = warpCol + ni * 8 + tg * 2;
            float rkh0 = subk[n * 256 + col], rkh1 = subk[n * 256 + col + 1];
            float rkx0 = subk[n * 256 + 128 + col], rkx1 = subk[n * 256 + 128 + col + 1];
#pragma unroll
            for (int h = 0; h < 2; h++) {
                int row = rowBase + warpRow + mi * 16 + g + h * 8;
                float sgw = d_sigw[row * 3 + n];
                float v0 = acc[mi][ni][h * 2 + 0] * sgw;
                float v1 = acc[mi][ni][h * 2 + 1] * sgw;
                d_agg[row * 384 + n * 128 + col] = v0;
                d_agg[row * 384 + n * 128 + col + 1] = v1;
                size_t so = (size_t)n * 131072 + (size_t)row * 128 + col;
                out_ss[so]     = rkh0 * v0 + ss[so] * rkx0;
                out_ss[so + 1] = rkh1 * v1 + ss[so + 1] * rkx1;
            }
        }
}

// ---------- K9: x_o GEMM via tf32 MMA, 64-row tiles ----------
__global__ __launch_bounds__(256) void k_final(const float* __restrict__ aw, const float* __restrict__ ab,
                                               const float* __restrict__ c0p, float* __restrict__ out) {
    __shared__ uint32_t As4[64 * LDAZ];
    __shared__ uint32_t Bs4[32 * LDBZ];
    int tid = threadIdx.x, lane = tid & 31, wid = tid >> 5;
    int colBase = blockIdx.x * 128, rowBase = blockIdx.y * 64;
    int warpRow = (wid & 1) * 32, warpCol = (wid >> 1) * 32;
    int g = lane >> 2, tg = lane & 3;
    int rsel = wid, n4 = lane * 4;
    int arow = tid >> 2, aseg = (tid & 3) * 8;

    float acc[2][4][4];
#pragma unroll
    for (int mi = 0; mi < 2; mi++)
#pragma unroll
        for (int ni = 0; ni < 4; ni++)
#pragma unroll
            for (int q = 0; q < 4; q++) acc[mi][ni][q] = 0.f;

    for (int kt = 0; kt < 384; kt += 32) {
        const float* src = d_agg + (size_t)(rowBase + arow) * 384 + kt + aseg;
#pragma unroll
        for (int q = 0; q < 2; q++) {
            float4 v = *(const float4*)(src + q * 4);
            uint4 w;
            w.x = f2tf(v.x); w.y = f2tf(v.y); w.z = f2tf(v.z); w.w = f2tf(v.w);
            *(uint4*)&As4[arow * LDAZ + aseg + q * 4] = w;
        }
#pragma unroll
        for (int i = 0; i < 4; i++) {
            int kl = i * 8 + rsel;
            float4 v = *(const float4*)(aw + (size_t)(kt + kl) * 512 + colBase + n4);
            uint4 w;
            w.x = f2tf(v.x); w.y = f2tf(v.y); w.z = f2tf(v.z); w.w = f2tf(v.w);
            *(uint4*)&Bs4[kl * LDBZ + n4] = w;
        }
        __syncthreads();
#pragma unroll
        for (int ks2 = 0; ks2 < 4; ks2++) {
            int k0 = ks2 * 8;
            uint32_t aF[2][4];
#pragma unroll
            for (int mi = 0; mi < 2; mi++) {
                int r = warpRow + mi * 16;
                aF[mi][0] = As4[(r + g) * LDAZ + k0 + tg];
                aF[mi][1] = As4[(r + 8 + g) * LDAZ + k0 + tg];
                aF[mi][2] = As4[(r + g) * LDAZ + k0 + tg + 4];
                aF[mi][3] = As4[(r + 8 + g) * LDAZ + k0 + tg + 4];
            }
            uint32_t bF[4][2];
#pragma unroll
            for (int ni = 0; ni < 4; ni++) {
                int c = warpCol + ni * 8 + g;
                bF[ni][0] = Bs4[(k0 + tg) * LDBZ + c];
                bF[ni][1] = Bs4[(k0 + tg + 4) * LDBZ + c];
            }
#pragma unroll
            for (int mi = 0; mi < 2; mi++)
#pragma unroll
                for (int ni = 0; ni < 4; ni++)
                    mma_tf32(acc[mi][ni], aF[mi], bF[ni]);
        }
        __syncthreads();
    }
#pragma unroll
    for (int mi = 0; mi < 2; mi++)
#pragma unroll
        for (int ni = 0; ni < 4; ni++) {
            int col = colBase + warpCol + ni * 8 + tg * 2;
#pragma unroll
            for (int h = 0; h < 2; h++) {
                int row = rowBase + warpRow + mi * 16 + g + h * 8;
#pragma unroll
                for (int c = 0; c < 2; c++) {
                    int cc = col + c;
                    float xo = sigm(acc[mi][ni][h * 2 + c] + ab[cc]);
                    float zi = d_z[(size_t)row * 1536 + cc];
                    float zf = d_z[(size_t)row * 1536 + 512 + cc];
                    float zc = d_z[(size_t)row * 1536 + 1024 + cc];
                    float cv = zf * c0p[(size_t)row * 512 + cc] + zi * zc;
                    out[(size_t)row * 512 + cc] = xo * tanhf(cv);
                    out[B_ * U_ + (size_t)row * 512 + cc] = cv;
                }
            }
        }
}

// ---------- launch ----------
extern "C" void kernel_launch(void* const* d_in, const int* in_sizes, int n_in,
                              void* d_out, int out_size) {
    const float* inputs   = (const float*)d_in[0];
    const float* h0       = (const float*)d_in[1];
    const float* c0       = (const float*)d_in[2];
    const float* sub_st   = (const float*)d_in[3];
    const float* kern     = (const float*)d_in[4];
    const float* rkern    = (const float*)d_in[5];
    const float* bias     = (const float*)d_in[6];
    const float* sub_k    = (const float*)d_in[7];
    const float* sub_rki  = (const float*)d_in[8];
    const float* sub_rks  = (const float*)d_in[9];
    const float* agg_w    = (const float*)d_in[10];
    const float* agg_b    = (const float*)d_in[11];
    const float* sub_lng  = (const float*)d_in[12];
    const float* sub_lnb  = (const float*)d_in[13];
    const float* sub_bw   = (const float*)d_in[14];
    const float* sub_sw   = (const float*)d_in[15];
    const float* g_skw    = (const float*)d_in[16];
    const float* g_skb    = (const float*)d_in[17];
    const float* k1_lng   = (const float*)d_in[18];
    const float* k1_lnb   = (const float*)d_in[19];
    const float* k1_base  = (const float*)d_in[20];
    const float* k1_spl   = (const float*)d_in[21];
    const float* k2_lng   = (const float*)d_in[22];
    const float* k2_lnb   = (const float*)d_in[23];
    const float* k2_base  = (const float*)d_in[24];
    const float* k2_spl   = (const float*)d_in[25];
    const float* gw       = (const float*)d_in[26];
    const float* gb       = (const float*)d_in[27];
    const float* sw       = (const float*)d_in[28];
    const float* sb       = (const float*)d_in[29];
    const float* lg       = (const float*)d_in[30];
    const float* lb       = (const float*)d_in[31];
    float* out = (float*)d_out;

    static bool attr_set = false;
    if (!attr_set) {
        cudaFuncSetAttribute(k_mega, cudaFuncAttributeMaxDynamicSharedMemorySize, SM_MEGA);
        attr_set = true;
    }

    k_mega<<<3200, 256, SM_MEGA>>>(inputs, k1_lng, k1_lnb, k1_base, k1_spl,
                                   g_skw, g_skb, h0, kern, rkern, bias,
                                   sub_st, sub_rki, sub_rks, sub_bw, sub_sw);
    k_mid<<<4096, 128>>>(k2_lng, k2_lnb, k2_base, k2_spl, gw, gb, sw, sb, lg, lb,
                         sub_lng, sub_lnb);
    k_subgemm<<<dim3(3, 16), 256>>>(sub_st, sub_k, out + 2 * B_ * U_);
    k_final<<<dim3(4, 16), 256>>>(agg_w, agg_b, c0, out);
}